// round 2
// baseline (speedup 1.0000x reference)
#include <cuda_runtime.h>

// Problem constants (fixed by the dataset).
#define BB 8
#define QQ 900
#define KK 1203
#define NN 100
#define TOTAL (BB * QQ * NN)   // 720000

// cost[b,q,n] = 2*cls + 5*l1 - 2*giou
//   cls  = focal-style class cost at gathered logit x = pred_logits[b,q,labels[b,n]]
//   l1   = sum |pred_box - tgt_box| (cxcywh)
//   giou = pairwise GIoU on xyxy boxes
__global__ void __launch_bounds__(256) matcher_cost_kernel(
    const float*  __restrict__ logits,   // (B,Q,K) fp32
    const float4* __restrict__ pboxes,   // (B,Q,4) as float4
    const int*    __restrict__ labels,   // (B,N) int32 (JAX demotes int64->int32)
    const float4* __restrict__ tboxes,   // (B,N,4) as float4
    float* __restrict__ out)             // (B,Q,N)
{
    int gid = blockIdx.x * blockDim.x + threadIdx.x;
    if (gid >= TOTAL) return;

    int n  = gid % NN;        // magic-number div by compiler
    int bq = gid / NN;        // = b*Q + q
    int b  = bq / QQ;
    int bn = b * NN + n;

    // ---- loads ----
    float4 pb = pboxes[bq];          // broadcast within warp (same q mostly)
    float4 tb = tboxes[bn];          // coalesced over n
    int lab = labels[bn];            // coalesced
    lab = min(max(lab, 0), KK - 1);  // defensive clamp (2 inst)
    float x = logits[(long)bq * KK + lab];  // gather within row

    // ---- focal class cost (3 MUFU: ex2, rcp, lg2) ----
    // p = sigmoid(x); L = log(1+exp(-x)) = -log(p); log(1-p) = -x - L
    float e  = __expf(-x);
    float s  = 1.0f + e;
    float p  = __fdividef(1.0f, s);
    float L  = __logf(s);
    float log1mp = -x - L;
    // clamp to match reference's log(max(.,1e-8)) — inactive for N(0,1) logits
    float logp = fmaxf(-L, -18.420681f);
    log1mp     = fmaxf(log1mp, -18.420681f);
    float omp  = 1.0f - p;
    // cls = -0.25*(1-p)^2*log(p) + 0.75*p^2*log(1-p)
    float cls = -0.25f * omp * omp * logp + 0.75f * p * p * log1mp;

    // ---- L1 box cost ----
    float l1 = fabsf(pb.x - tb.x) + fabsf(pb.y - tb.y)
             + fabsf(pb.z - tb.z) + fabsf(pb.w - tb.w);

    // ---- GIoU (1 MUFU) ----
    float px0 = pb.x - 0.5f * pb.z, px1 = pb.x + 0.5f * pb.z;
    float py0 = pb.y - 0.5f * pb.w, py1 = pb.y + 0.5f * pb.w;
    float tx0 = tb.x - 0.5f * tb.z, tx1 = tb.x + 0.5f * tb.z;
    float ty0 = tb.y - 0.5f * tb.w, ty1 = tb.y + 0.5f * tb.w;
    float area1 = pb.z * pb.w;
    float area2 = tb.z * tb.w;

    float wi = fmaxf(fminf(px1, tx1) - fmaxf(px0, tx0), 0.0f);
    float hi = fmaxf(fminf(py1, ty1) - fmaxf(py0, ty0), 0.0f);
    float inter = wi * hi;
    float uni   = area1 + area2 - inter;

    float wc = fmaxf(px1, tx1) - fminf(px0, tx0);   // >= 0 always (w,h >= 0)
    float hc = fmaxf(py1, ty1) - fminf(py0, ty0);
    float ac = wc * hc;

    // giou = inter/uni - (ac - uni)/ac  ==  (ac*(inter-uni) + uni*uni) / (uni*ac)
    float num  = ac * (inter - uni) + uni * uni;
    float giou = num * __fdividef(1.0f, uni * ac);

    out[gid] = 2.0f * cls + 5.0f * l1 - 2.0f * giou;
}

extern "C" void kernel_launch(void* const* d_in, const int* in_sizes, int n_in,
                              void* d_out, int out_size)
{
    const float*  logits = (const float*)d_in[0];
    const float4* pboxes = (const float4*)d_in[1];
    const int*    labels = (const int*)d_in[2];
    const float4* tboxes = (const float4*)d_in[3];
    float* out = (float*)d_out;

    const int threads = 256;
    const int blocks  = (TOTAL + threads - 1) / threads;
    matcher_cost_kernel<<<blocks, threads>>>(logits, pboxes, labels, tboxes, out);
}

// round 3
// speedup vs baseline: 1.0332x; 1.0332x over previous
#include <cuda_runtime.h>

// Problem constants (fixed by the dataset).
#define BB 8
#define QQ 900
#define KK 1203
#define NN 100
#define NQUAD (NN / 4)                 // 25 quads of n per (b,q) row
#define TOTAL4 (BB * QQ * NQUAD)       // 180000 threads, 4 outputs each

// cost[b,q,n] = 2*cls + 5*l1 - 2*giou
__global__ void __launch_bounds__(256) matcher_cost_kernel(
    const float*  __restrict__ logits,   // (B,Q,K) fp32
    const float4* __restrict__ pboxes,   // (B,Q,4)
    const int4*   __restrict__ labels4,  // (B,N) int32, read as int4
    const float4* __restrict__ tboxes,   // (B,N,4)
    float4* __restrict__ out4)           // (B,Q,N) as float4 quads
{
    int gid = blockIdx.x * blockDim.x + threadIdx.x;
    if (gid >= TOTAL4) return;

    int quad = gid % NQUAD;              // which group of 4 n's
    int bq   = gid / NQUAD;              // b*Q + q
    int b    = bq / QQ;

    // ---- per-thread loads, front-batched ----
    int4 lab4 = labels4[b * NQUAD + quad];            // 4 labels, 16B coalesced
    const float* lrow = logits + (long)bq * KK;
    // 4 independent scattered gathers (streaming hint: no reuse beyond row)
    float x0 = __ldcs(lrow + min(max(lab4.x, 0), KK - 1));
    float x1 = __ldcs(lrow + min(max(lab4.y, 0), KK - 1));
    float x2 = __ldcs(lrow + min(max(lab4.z, 0), KK - 1));
    float x3 = __ldcs(lrow + min(max(lab4.w, 0), KK - 1));

    int bn = b * NN + quad * 4;
    float4 tb0 = tboxes[bn + 0];
    float4 tb1 = tboxes[bn + 1];
    float4 tb2 = tboxes[bn + 2];
    float4 tb3 = tboxes[bn + 3];
    float4 pb  = pboxes[bq];             // broadcast within most of a warp

    // ---- per-(b,q) precompute (amortized over 4 outputs) ----
    float px0 = pb.x - 0.5f * pb.z, px1 = pb.x + 0.5f * pb.z;
    float py0 = pb.y - 0.5f * pb.w, py1 = pb.y + 0.5f * pb.w;
    float area1 = pb.z * pb.w;

    float4 res;
    float* resp = &res.x;
    float xs[4] = {x0, x1, x2, x3};
    float4 tbs[4] = {tb0, tb1, tb2, tb3};

    #pragma unroll
    for (int i = 0; i < 4; i++) {
        float x = xs[i];
        float4 tb = tbs[i];

        // ---- focal class cost (3 MUFU) ----
        // p = sigmoid(x); L = log(1+exp(-x)) = -log(p); log(1-p) = -x - L
        float e  = __expf(-x);
        float s  = 1.0f + e;
        float p  = __fdividef(1.0f, s);
        float L  = __logf(s);
        float logp   = fmaxf(-L, -18.420681f);     // log(max(p,1e-8))
        float log1mp = fmaxf(-x - L, -18.420681f); // log(max(1-p,1e-8))
        float omp = 1.0f - p;
        float cls = -0.25f * omp * omp * logp + 0.75f * p * p * log1mp;

        // ---- L1 box cost ----
        float l1 = fabsf(pb.x - tb.x) + fabsf(pb.y - tb.y)
                 + fabsf(pb.z - tb.z) + fabsf(pb.w - tb.w);

        // ---- GIoU (1 MUFU) ----
        float tx0 = tb.x - 0.5f * tb.z, tx1 = tb.x + 0.5f * tb.z;
        float ty0 = tb.y - 0.5f * tb.w, ty1 = tb.y + 0.5f * tb.w;
        float area2 = tb.z * tb.w;

        float wi = fmaxf(fminf(px1, tx1) - fmaxf(px0, tx0), 0.0f);
        float hi = fmaxf(fminf(py1, ty1) - fmaxf(py0, ty0), 0.0f);
        float inter = wi * hi;
        float uni   = area1 + area2 - inter;

        float wc = fmaxf(px1, tx1) - fminf(px0, tx0);   // >= 0 (w,h >= 0)
        float hc = fmaxf(py1, ty1) - fminf(py0, ty0);
        float ac = wc * hc;

        // giou = inter/uni - (ac-uni)/ac = (ac*(inter-uni) + uni*uni)/(uni*ac)
        float num  = ac * (inter - uni) + uni * uni;
        float giou = num * __fdividef(1.0f, uni * ac);

        resp[i] = 2.0f * cls + 5.0f * l1 - 2.0f * giou;
    }

    out4[gid] = res;   // STG.128, fully coalesced (row=400B, quad offsets 16B-aligned)
}

extern "C" void kernel_launch(void* const* d_in, const int* in_sizes, int n_in,
                              void* d_out, int out_size)
{
    const float*  logits  = (const float*)d_in[0];
    const float4* pboxes  = (const float4*)d_in[1];
    const int4*   labels4 = (const int4*)d_in[2];
    const float4* tboxes  = (const float4*)d_in[3];
    float4* out4 = (float4*)d_out;

    const int threads = 256;
    const int blocks  = (TOTAL4 + threads - 1) / threads;
    matcher_cost_kernel<<<blocks, threads>>>(logits, pboxes, labels4, tboxes, out4);
}